// round 17
// baseline (speedup 1.0000x reference)
#include <cuda_runtime.h>
#include <cuda_fp16.h>

typedef unsigned long long ull;

// Problem constants
constexpr int H   = 75;
constexpr int H3  = 225;
constexpr int H4  = 300;
constexpr int D2  = 150;
constexpr int NB  = 256;
constexpr int LQ  = 64;
constexpr int LP  = 500;

constexpr int G    = 2;               // items per block (2 pipelines/SM)
constexpr int NTH  = 256;
constexpr int NBLK = (2 * NB) / G;    // 256 blocks -> ~2 blocks/SM

constexpr int KB8 = 38;               // Wg/Wih fp16 k-blocks (304 slots)
constexpr int KBG = 19;               // WPu k-blocks (150->152)
constexpr int KBH = 10;               // Whh/WPv k-blocks (75->80)
constexpr int QPS = 76;

// Shared-memory layout (float-slot offsets)
constexpr int HP   = 76;
constexpr int CCS  = 304;             // [p 0..149 | 00 | c 152..301 | 00]
constexpr int GIS  = 227;

constexpr int OFF_QPH  = 0;                      // [G][LQ][76] halves = 4864 slots
constexpr int OFF_WHH  = 4864;                   // [10][225][8] halves = 9000
constexpr int OFF_WPV  = OFF_WHH + 9000;         // [10][75][8]  = 3000
constexpr int OFF_WPU  = OFF_WPV + 3000;         // [19][75][8]  = 5700
constexpr int OFF_H    = OFF_WPU + 5700;         // [G][76]
constexpr int OFF_V    = OFF_H + G * HP;
constexpr int OFF_E    = OFF_V + G * HP;
constexpr int OFF_S    = OFF_E + G * HP;         // [G][64]
constexpr int OFF_PART = OFF_S + G * LQ;         // [2][G][64]
constexpr int OFF_CC   = OFF_PART + 2 * G * LQ;  // [G][304]
constexpr int OFF_X    = OFF_CC + G * CCS;       // [G][304] contiguous x 0..299
constexpr int OFF_GI   = OFF_X + G * CCS;        // [G][227]
constexpr int OFF_GH   = OFF_GI + G * GIS;       // [G][227]
constexpr int SMEM_FLOATS = OFF_GH + G * GIS;    // 25528 slots
constexpr int SMEM_BYTES  = SMEM_FLOATS * 4;     // 102112 B -> 2 blocks/SM fits

static_assert((OFF_WHH * 4) % 16 == 0 && (OFF_WPV * 4) % 16 == 0, "align");
static_assert((OFF_WPU * 4) % 16 == 0 && (OFF_H * 4) % 16 == 0, "align");
static_assert((OFF_CC * 4) % 16 == 0 && (OFF_X * 4) % 16 == 0, "align");
static_assert(2 * SMEM_BYTES <= 227 * 1024, "2-block residency");

// Device scratch
__device__ __half g_QprojH[LQ * NB * H];
__device__ float  g_WQuT[D2 * H];
// Wg packed in CC-slot space: slot s -> k = s (<150) | zero (150,151) | s-2 (152..301) | zero
__device__ __align__(16) __half g_Wg4h[KB8 * H4 * 8];
__device__ __align__(16) __half g_Wih4h[2][KB8 * H3 * 8];   // contiguous k 0..299 + 4 zeros

// ---------- math helpers ----------
__device__ __forceinline__ float tanha(float x) {
    float r; asm("tanh.approx.f32 %0, %1;" : "=f"(r) : "f"(x)); return r;
}
__device__ __forceinline__ float siga(float x) {
    return fmaf(tanha(0.5f * x), 0.5f, 0.5f);
}
__device__ __forceinline__ ull pack2(float x, float y) {
    ull r; asm("mov.b64 %0, {%1, %2};" : "=l"(r) : "f"(x), "f"(y)); return r;
}
__device__ __forceinline__ void fma2(ull& d, ull a, ull b) {
    asm("fma.rn.f32x2 %0, %1, %2, %0;" : "+l"(d) : "l"(a), "l"(b));
}
__device__ __forceinline__ float hsum2(ull a) {
    float x, y; asm("mov.b64 {%0, %1}, %2;" : "=f"(x), "=f"(y) : "l"(a));
    return x + y;
}
__device__ __forceinline__ ull h2f2(unsigned v) {
    float2 f = __half22float2(*reinterpret_cast<const __half2*>(&v));
    return pack2(f.x, f.y);
}

#define LD2(p, idx) (*reinterpret_cast<const ulonglong2*>((p) + (idx)))

// ---------- prep ----------
__global__ void prep_kernel(const float* __restrict__ WQu,
                            const float* __restrict__ Wg,
                            const float* __restrict__ Wf,
                            const float* __restrict__ Wr) {
    int o = blockIdx.x * blockDim.x + threadIdx.x;
    if (o < D2 * H) {
        int k = o / H, j = o - k * H;
        g_WQuT[o] = WQu[j * D2 + k];
    } else if (o < D2 * H + KB8 * H4 * 8) {            // Wg slot-aware pack
        int o2 = o - D2 * H;
        int kb = o2 / 2400, r = o2 % 2400, j = r >> 3, c = r & 7;
        int s = kb * 8 + c;                             // CC slot index
        int k = (s < D2) ? s : ((s >= 152 && s < 302) ? s - 2 : -1);
        g_Wg4h[o2] = __float2half(k >= 0 ? Wg[j * H4 + k] : 0.0f);
    } else if (o < D2 * H + KB8 * H4 * 8 + 2 * KB8 * H3 * 8) {
        int o2 = o - D2 * H - KB8 * H4 * 8;
        int d = o2 / (KB8 * H3 * 8);
        int o3 = o2 - d * (KB8 * H3 * 8);
        int kb = o3 / 1800, r = o3 % 1800, j = r >> 3, c = r & 7;
        int k = kb * 8 + c;
        const float* W = d ? Wr : Wf;
        g_Wih4h[d][o3] = __float2half(k < H4 ? W[j * H4 + k] : 0.0f);
    }
}
constexpr int PREP_N = D2 * H + KB8 * H4 * 8 + 2 * KB8 * H3 * 8;

// ---------- Qproj ----------
__global__ void qproj_kernel(const float* __restrict__ X,
                             const float* __restrict__ bias) {
    int o = blockIdx.x * blockDim.x + threadIdx.x;
    if (o >= LQ * NB * H) return;
    int m = o / H;
    int j = o - m * H;
    const float* xr = X + (size_t)m * D2;
    float acc = bias[j];
#pragma unroll 15
    for (int k = 0; k < D2; k++) acc = fmaf(xr[k], g_WQuT[k * H + j], acc);
    g_QprojH[o] = __float2half(acc);
}

// ---------- persistent kernel: 2 items/block, 2 blocks/SM ----------
__global__ __launch_bounds__(NTH, 2)
void persist_kernel(const float* __restrict__ quesEnc,
                    const float* __restrict__ passEnc,
                    const float* __restrict__ WPu_w, const float* __restrict__ WPu_b,
                    const float* __restrict__ WPv_w, const float* __restrict__ WPv_b,
                    const float* __restrict__ Wg_b,
                    const float* __restrict__ Vt,
                    const float* __restrict__ Whh_f,
                    const float* __restrict__ bih_f, const float* __restrict__ bhh_f,
                    const float* __restrict__ Whh_r,
                    const float* __restrict__ bih_r, const float* __restrict__ bhh_r,
                    const float* __restrict__ h0f,   const float* __restrict__ h0r,
                    float* __restrict__ out) {
    extern __shared__ float sm[];
    __half* qph  = reinterpret_cast<__half*>(sm + OFF_QPH);
    __half* whhH = reinterpret_cast<__half*>(sm + OFF_WHH);
    __half* wpvH = reinterpret_cast<__half*>(sm + OFF_WPV);
    __half* wpuH = reinterpret_cast<__half*>(sm + OFF_WPU);
    const int tid   = threadIdx.x;
    const int item0 = blockIdx.x * G;
    const int dir   = item0 >> 8;

    // ---- one-time smem fills ----
    {
        const float* Whh = dir ? Whh_r : Whh_f;
        for (int idx = tid; idx < KBH * H3 * 8; idx += NTH) {     // WhhT fp16
            int kb = idx / 1800, r = idx % 1800, rr = r >> 3, c = r & 7;
            int k = kb * 8 + c;
            whhH[idx] = __float2half(k < H ? Whh[rr * H + k] : 0.0f);
        }
        for (int idx = tid; idx < KBH * H * 8; idx += NTH) {      // WPvT fp16
            int kb = idx / 600, r = idx % 600, j = r >> 3, c = r & 7;
            int k = kb * 8 + c;
            wpvH[idx] = __float2half(k < H ? WPv_w[j * H + k] : 0.0f);
        }
        for (int idx = tid; idx < KBG * H * 8; idx += NTH) {      // WPuT fp16
            int kb = idx / 600, r = idx % 600, j = r >> 3, c = r & 7;
            int k = kb * 8 + c;
            wpuH[idx] = __float2half(k < D2 ? WPu_w[j * D2 + k] : 0.0f);
        }
        const float* h0 = dir ? h0r : h0f;
        for (int idx = tid; idx < G * HP; idx += NTH) {
            int i = idx / HP, j = idx % HP;
            int b = (item0 + i) & 255;
            sm[OFF_H + idx] = (j < H) ? h0[b * H + j] : 0.0f;
            sm[OFF_V + idx] = (j < H) ? Vt[b * H + j] : 0.0f;
            sm[OFF_E + idx] = 0.0f;
        }
        for (int idx = tid; idx < 2 * G * CCS; idx += NTH)        // zero CC + X (pads!)
            sm[OFF_CC + idx] = 0.0f;
        for (int idx = tid; idx < G * LQ * QPS; idx += NTH) {     // Qproj fp16 slice
            int i = idx / (LQ * QPS);
            int r = idx - i * (LQ * QPS);
            int q = r / QPS, j = r - q * QPS;
            int b = (item0 + i) & 255;
            qph[idx] = (j < H) ? g_QprojH[((size_t)q * NB + b) * H + j]
                               : __float2half(0.0f);
        }
        int te0 = dir ? (LP - 1) : 0;
        for (int idx = tid; idx < G * D2; idx += NTH) {           // p(0)
            int i = idx / D2, d = idx - i * D2;
            int b = (item0 + i) & 255;
            sm[OFF_CC + i * CCS + d] = passEnc[((size_t)te0 * NB + b) * D2 + d];
        }
    }

    // ---- hoisted per-thread constants ----
    const int i1 = tid / H, j1 = tid % H;                 // p1-e (tid<150) / p7
    const bool p1_act = (tid < G * H);
    const float b_ph1 = p1_act ? (WPu_b[j1] + WPv_b[j1]) : 0.0f;

    const int half = tid & 1, pair = tid >> 1;            // p2: 2 threads / (i,q)
    const int i2 = pair >> 6, q2 = pair & 63;
    const __half2* qp2 = reinterpret_cast<const __half2*>(qph + i2 * (LQ * QPS) + q2 * QPS)
                         + (half ? 19 : 0);
    const float2* ee2 = reinterpret_cast<const float2*>(sm + OFF_E + i2 * HP) + (half ? 19 : 0);
    const float2* vv2 = reinterpret_cast<const float2*>(sm + OFF_V + i2 * HP) + (half ? 19 : 0);

    const float b_ih = (tid < H3) ? (dir ? bih_r : bih_f)[tid] : 0.0f;  // p6 row/thread
    const float* bhh_d = dir ? bhh_r : bhh_f;

    const uint4* wg_all = reinterpret_cast<const uint4*>(g_Wg4h);
    const uint4* wi_all = reinterpret_cast<const uint4*>(g_Wih4h[dir]);
    const uint4* whh_u4 = reinterpret_cast<const uint4*>(whhH);
    const uint4* wpv_u4 = reinterpret_cast<const uint4*>(wpvH);
    const uint4* wpu_u4 = reinterpret_cast<const uint4*>(wpuH);

    const ull* x0c = reinterpret_cast<const ull*>(sm + OFF_CC);
    const ull* x1c = reinterpret_cast<const ull*>(sm + OFF_CC + CCS);
    const ull* x0x = reinterpret_cast<const ull*>(sm + OFF_X);
    const ull* x1x = reinterpret_cast<const ull*>(sm + OFF_X + CCS);
    const ull* hh0 = reinterpret_cast<const ull*>(sm + OFF_H);
    const ull* hh1 = reinterpret_cast<const ull*>(sm + OFF_H + HP);

    __syncthreads();

    // ================= main 500-step loop =================
    for (int t = 0; t < LP; t++) {
        float pf0 = 0.0f, pf1 = 0.0f, pf2 = 0.0f;   // p(t+1) prefetch regs

        // ---- phase 1: e = WPu@p + WPv@h (tid<150) || gh = Whh@h (tid 150..255) ----
        if (p1_act) {
            ull aA = pack2(b_ph1, 0.0f), aB = 0ull;
            const ull* pp = i1 ? x1c : x0c;
            const ull* hh = i1 ? hh1 : hh0;
#pragma unroll
            for (int kb = 0; kb < KBG; kb++) {              // WPu @ p
                uint4 w = wpu_u4[kb * H + j1];
                ull w0 = h2f2(w.x), w1 = h2f2(w.y), w2 = h2f2(w.z), w3 = h2f2(w.w);
                ulonglong2 pa = LD2(pp, 4 * kb), pb = LD2(pp, 4 * kb + 2);
                fma2(aA, w0, pa.x); fma2(aB, w1, pa.y);
                fma2(aA, w2, pb.x); fma2(aB, w3, pb.y);
            }
#pragma unroll
            for (int kb = 0; kb < KBH; kb++) {              // WPv @ h
                uint4 w = wpv_u4[kb * H + j1];
                ull w0 = h2f2(w.x), w1 = h2f2(w.y), w2 = h2f2(w.z), w3 = h2f2(w.w);
                ulonglong2 pa = LD2(hh, 4 * kb), pb = LD2(hh, 4 * kb + 2);
                fma2(aA, w0, pa.x); fma2(aB, w1, pa.y);
                fma2(aA, w2, pb.x); fma2(aB, w3, pb.y);
            }
            sm[OFF_E + i1 * HP + j1] = hsum2(aA) + hsum2(aB);
        } else {
            for (int rr = tid - 150; rr < H3; rr += 106) {
                ull a0A = 0, a0B = 0, a1A = 0, a1B = 0;
#pragma unroll
                for (int kb = 0; kb < KBH; kb++) {
                    uint4 w = whh_u4[kb * H3 + rr];
                    ull w0 = h2f2(w.x), w1 = h2f2(w.y), w2 = h2f2(w.z), w3 = h2f2(w.w);
                    ulonglong2 pa, pb;
                    pa = LD2(hh0, 4 * kb); pb = LD2(hh0, 4 * kb + 2);
                    fma2(a0A, w0, pa.x); fma2(a0B, w1, pa.y); fma2(a0A, w2, pb.x); fma2(a0B, w3, pb.y);
                    pa = LD2(hh1, 4 * kb); pb = LD2(hh1, 4 * kb + 2);
                    fma2(a1A, w0, pa.x); fma2(a1B, w1, pa.y); fma2(a1A, w2, pb.x); fma2(a1B, w3, pb.y);
                }
                float bb = bhh_d[rr];
                sm[OFF_GH + 0 * GIS + rr] = hsum2(a0A) + hsum2(a0B) + bb;
                sm[OFF_GH + 1 * GIS + rr] = hsum2(a1A) + hsum2(a1B) + bb;
            }
        }
        __syncthreads();

        // ---- phase 2: attention scores (all 256 threads; 2 per (i,q), j-split) ----
        {
            float acc = 0.0f;
#pragma unroll
            for (int u = 0; u < 19; u++) {
                float2 qp = __half22float2(qp2[u]);
                float2 e = ee2[u], v = vv2[u];
                acc = fmaf(tanha(qp.x + e.x), v.x, acc);
                acc = fmaf(tanha(qp.y + e.y), v.y, acc);
            }
            sm[OFF_PART + half * (G * LQ) + i2 * LQ + q2] = acc;
        }
        __syncthreads();

        // ---- phase 3: softmax (warp w = item w) ----
        {
            int wid = tid >> 5, lane = tid & 31;
            if (wid < G) {
                float v0 = sm[OFF_PART + wid * LQ + lane]      + sm[OFF_PART + G * LQ + wid * LQ + lane];
                float v1 = sm[OFF_PART + wid * LQ + lane + 32] + sm[OFF_PART + G * LQ + wid * LQ + lane + 32];
                float m = fmaxf(v0, v1);
#pragma unroll
                for (int o = 16; o > 0; o >>= 1) m = fmaxf(m, __shfl_xor_sync(0xffffffffu, m, o));
                float e0 = __expf(v0 - m), e1 = __expf(v1 - m);
                float s = e0 + e1;
#pragma unroll
                for (int o = 16; o > 0; o >>= 1) s += __shfl_xor_sync(0xffffffffu, s, o);
                float inv = __fdividef(1.0f, s);
                sm[OFF_S + wid * LQ + lane]      = e0 * inv;
                sm[OFF_S + wid * LQ + lane + 32] = e1 * inv;
            }
        }
        __syncthreads();

        // ---- phase 4: context c -> cc slots [152..301] (tid<150, float2) ----
        if (tid < G * 75) {
            int i = tid / 75, d2 = tid % 75;
            int b = (item0 + i) & 255;
            const float2* qe2 = reinterpret_cast<const float2*>(quesEnc + (size_t)b * D2) + d2;
            const float4* a4 = reinterpret_cast<const float4*>(sm + OFF_S + i * LQ);
            float ax = 0.0f, ay = 0.0f;
#pragma unroll
            for (int q4 = 0; q4 < 16; q4++) {
                float4 av = a4[q4];
                float2 v0 = qe2[(4 * q4 + 0) * (NB * 75)];
                float2 v1 = qe2[(4 * q4 + 1) * (NB * 75)];
                float2 v2 = qe2[(4 * q4 + 2) * (NB * 75)];
                float2 v3 = qe2[(4 * q4 + 3) * (NB * 75)];
                ax = fmaf(av.x, v0.x, ax); ay = fmaf(av.x, v0.y, ay);
                ax = fmaf(av.y, v1.x, ax); ay = fmaf(av.y, v1.y, ay);
                ax = fmaf(av.z, v2.x, ax); ay = fmaf(av.z, v2.y, ay);
                ax = fmaf(av.w, v3.x, ax); ay = fmaf(av.w, v3.y, ay);
            }
            reinterpret_cast<float2*>(sm + OFF_CC + i * CCS)[76 + d2] = make_float2(ax, ay);
        } else if (tid >= 156 && tid < 256) {
            // passEnc prefetch for t+1 (100 threads x 3 elems)
            int u = tid - 156;
            int tn = (t + 1 < LP) ? t + 1 : t;
            int ten = dir ? (LP - 1 - tn) : tn;
#pragma unroll
            for (int c = 0; c < 3; c++) {
                int e = 3 * u + c;
                int i = e / D2, d = e - i * D2;
                int b = (item0 + i) & 255;
                float v = passEnc[((size_t)ten * NB + b) * D2 + d];
                if (c == 0) pf0 = v; else if (c == 1) pf1 = v; else pf2 = v;
            }
        }
        __syncthreads();

        // ---- phase 5: x = siga(Wg@cc + b)*cc (slot-packed fp16 global stream) ----
        for (int row = tid; row < H4; row += NTH) {
            ull a0A = 0, a0B = 0, a1A = 0, a1B = 0;
#pragma unroll 19
            for (int kb = 0; kb < KB8; kb++) {
                uint4 w = wg_all[kb * H4 + row];
                ull w0 = h2f2(w.x), w1 = h2f2(w.y), w2 = h2f2(w.z), w3 = h2f2(w.w);
                ulonglong2 pa, pb;
                pa = LD2(x0c, 4 * kb); pb = LD2(x0c, 4 * kb + 2);
                fma2(a0A, w0, pa.x); fma2(a0B, w1, pa.y); fma2(a0A, w2, pb.x); fma2(a0B, w3, pb.y);
                pa = LD2(x1c, 4 * kb); pb = LD2(x1c, 4 * kb + 2);
                fma2(a1A, w0, pa.x); fma2(a1B, w1, pa.y); fma2(a1A, w2, pb.x); fma2(a1B, w3, pb.y);
            }
            float bg = Wg_b[row];
            int cs = (row < D2) ? row : row + 2;            // cc slot for dim row
            sm[OFF_X + 0 * CCS + row] = siga(hsum2(a0A) + hsum2(a0B) + bg) * sm[OFF_CC + 0 * CCS + cs];
            sm[OFF_X + 1 * CCS + row] = siga(hsum2(a1A) + hsum2(a1B) + bg) * sm[OFF_CC + 1 * CCS + cs];
        }
        __syncthreads();

        // ---- phase 6: gi = Wih@x + bih (row/thread, fp16 global stream) ----
        if (tid < H3) {
            ull a0A = 0, a0B = 0, a1A = 0, a1B = 0;
#pragma unroll 19
            for (int kb = 0; kb < KB8; kb++) {
                uint4 w = wi_all[kb * H3 + tid];
                ull w0 = h2f2(w.x), w1 = h2f2(w.y), w2 = h2f2(w.z), w3 = h2f2(w.w);
                ulonglong2 pa, pb;
                pa = LD2(x0x, 4 * kb); pb = LD2(x0x, 4 * kb + 2);
                fma2(a0A, w0, pa.x); fma2(a0B, w1, pa.y); fma2(a0A, w2, pb.x); fma2(a0B, w3, pb.y);
                pa = LD2(x1x, 4 * kb); pb = LD2(x1x, 4 * kb + 2);
                fma2(a1A, w0, pa.x); fma2(a1B, w1, pa.y); fma2(a1A, w2, pb.x); fma2(a1B, w3, pb.y);
            }
            sm[OFF_GI + 0 * GIS + tid] = hsum2(a0A) + hsum2(a0B) + b_ih;
            sm[OFF_GI + 1 * GIS + tid] = hsum2(a1A) + hsum2(a1B) + b_ih;
        }
        __syncthreads();

        // ---- phase 7: GRU combine + out (tid<150) || store p(t+1) (156..255) ----
        if (tid < G * H) {
            int i = i1, j = j1;
            float gr  = sm[OFF_GI + i * GIS + j]         + sm[OFF_GH + i * GIS + j];
            float gz  = sm[OFF_GI + i * GIS + H + j]     + sm[OFF_GH + i * GIS + H + j];
            float gin = sm[OFF_GI + i * GIS + 2 * H + j];
            float ghn = sm[OFF_GH + i * GIS + 2 * H + j];
            float r = siga(gr);
            float z = siga(gz);
            float n = tanha(fmaf(r, ghn, gin));
            float hn = (1.0f - z) * n + z * sm[OFF_H + i * HP + j];
            sm[OFF_H + i * HP + j] = hn;
            int b = (item0 + i) & 255;
            out[((size_t)t * NB + b) * D2 + dir * H + j] = hn;
        } else if (tid >= 156 && tid < 256) {
            int u = tid - 156;
#pragma unroll
            for (int c = 0; c < 3; c++) {
                int e = 3 * u + c;
                int i = e / D2, d = e - i * D2;
                float v = (c == 0) ? pf0 : (c == 1) ? pf1 : pf2;
                sm[OFF_CC + i * CCS + d] = v;
            }
        }
        __syncthreads();
    }
}

extern "C" void kernel_launch(void* const* d_in, const int* in_sizes, int n_in,
                              void* d_out, int out_size) {
    const float* quesEnc = (const float*)d_in[0];
    const float* passEnc = (const float*)d_in[1];
    const float* WQu_w   = (const float*)d_in[2];
    const float* WQu_b   = (const float*)d_in[3];
    const float* WPu_w   = (const float*)d_in[4];
    const float* WPu_b   = (const float*)d_in[5];
    const float* WPv_w   = (const float*)d_in[6];
    const float* WPv_b   = (const float*)d_in[7];
    const float* Wg_w    = (const float*)d_in[8];
    const float* Wg_b    = (const float*)d_in[9];
    const float* Vt      = (const float*)d_in[10];
    const float* Wih_f   = (const float*)d_in[11];
    const float* Whh_f   = (const float*)d_in[12];
    const float* bih_f   = (const float*)d_in[13];
    const float* bhh_f   = (const float*)d_in[14];
    const float* Wih_r   = (const float*)d_in[15];
    const float* Whh_r   = (const float*)d_in[16];
    const float* bih_r   = (const float*)d_in[17];
    const float* bhh_r   = (const float*)d_in[18];
    const float* h0f     = (const float*)d_in[19];
    const float* h0r     = (const float*)d_in[20];
    float* out = (float*)d_out;

    cudaFuncSetAttribute(persist_kernel,
                         cudaFuncAttributeMaxDynamicSharedMemorySize, SMEM_BYTES);

    prep_kernel<<<(PREP_N + 255) / 256, 256>>>(WQu_w, Wg_w, Wih_f, Wih_r);
    qproj_kernel<<<(LQ * NB * H + 255) / 256, 256>>>(quesEnc, WQu_b);
    persist_kernel<<<NBLK, NTH, SMEM_BYTES>>>(quesEnc, passEnc,
                                              WPu_w, WPu_b, WPv_w, WPv_b,
                                              Wg_b, Vt,
                                              Whh_f, bih_f, bhh_f,
                                              Whh_r, bih_r, bhh_r,
                                              h0f, h0r, out);
}